// round 4
// baseline (speedup 1.0000x reference)
#include <cuda_runtime.h>

#define NQ 16
#define BATCH 512
#define NH 16            // 2^4 folded-high-qubit values (qubits 12..15)
#define TILE 4096        // 2^12 amplitudes per CTA
#define THREADS 256

// Partial <Z_i> sums per (h, sample): 16 * 512 * 16 floats = 512 KB scratch.
__device__ float g_partial[NH * BATCH * NQ];

__device__ __forceinline__ unsigned mask_q(int q) {
    // rows of A^{-1} for the CNOT ring: x_q = parity(y & m_q)
    if (q == 0) return 0x8001u;          // bits {0,15}
    if (q == 1) return 0x8003u;          // bits {0,1,15}
    return 3u << (q - 1);                // bits {q-1, q}
}

__global__ __launch_bounds__(THREADS) void qsim_kernel(
    const float* __restrict__ z,
    const float* __restrict__ params,
    const float* __restrict__ w)   // ent_weights [2,16]
{
    const int h   = blockIdx.x;    // value of y bits 12..15
    const int b   = blockIdx.y;    // sample
    const int tid = threadIdx.x;
    const int lane = tid & 31;
    const int wq   = tid >> 5;     // warp 0..7

    __shared__ float2 st[TILE + (TILE >> 4)];          // padded exchange buffer
    __shared__ float PL[256], PH[256];                 // magnitude product tables (x-basis)
    __shared__ unsigned short XL[256], XH[256];        // A^{-1} byte-xor tables
    __shared__ float2 Gs[16];                          // folded 4-qubit gate row G[h,u]
    __shared__ float ce[16], se[16], c2[16], s2[16];
    __shared__ float wsum[8][16];

    // ---- stage 1: angles ----
    if (tid < 16) {
        float phi = z[b * NQ + tid] + params[tid] + w[tid];   // merged RX angles
        ce[tid] = cosf(0.5f * phi);
        se[tid] = sinf(0.5f * phi);
        float th = w[NQ + tid];                               // layer-1 RX angles
        c2[tid] = cosf(0.5f * th);
        s2[tid] = sinf(0.5f * th);
    }
    __syncthreads();

    // ---- stage 2: tables (one entry per thread) ----
    {
        int idx = tid;
        float pl = 1.f, ph = 1.f;
        unsigned xl = 0, xh = 0;
#pragma unroll
        for (int q = 0; q < 8; q++) {
            pl *= ((idx >> q) & 1) ? se[q]     : ce[q];
            ph *= ((idx >> q) & 1) ? se[8 + q] : ce[8 + q];
        }
#pragma unroll
        for (int q = 0; q < 16; q++) {
            unsigned m = mask_q(q);
            xl |= (unsigned)(__popc(idx & (m & 0xFFu)) & 1) << q;
            xh |= (unsigned)(__popc(idx & (m >> 8))    & 1) << q;
        }
        PL[idx] = pl; PH[idx] = ph;
        XL[idx] = (unsigned short)xl; XH[idx] = (unsigned short)xh;
    }
    if (tid < 16) {
        int u = tid, d = h ^ u;
        float mag = 1.f;
#pragma unroll
        for (int j = 0; j < 4; j++)
            mag *= ((d >> j) & 1) ? s2[12 + j] : c2[12 + j];
        int k = __popc(d) & 3;                 // G = (-i)^k * mag
        float2 g;
        g.x = (k == 0) ? mag : ((k == 2) ? -mag : 0.f);
        g.y = (k == 1) ? -mag : ((k == 3) ? mag : 0.f);
        Gs[u] = g;
    }
    __syncthreads();

    // ---- stage 3: construct amp(h, low) = sum_u G[h,u] * psi1(u<<12 | low) ----
    // element low = (wq<<9)|(lane<<4)|c  (bits 0..3 = c, 4..8 = lane, 9..11 = wq)
    float sre[16], sim[16];
    const int hi4 = (wq << 1) | (lane >> 4);   // (low>>8), thread-constant
    unsigned xl[16];
#pragma unroll
    for (int c = 0; c < 16; c++) {
        xl[c] = XL[((lane & 15) << 4) | c];
        sre[c] = 0.f; sim[c] = 0.f;
    }
    for (int u = 0; u < 16; u++) {
        float2 g = Gs[u];
        unsigned xh = XH[(u << 4) | hi4];
#pragma unroll
        for (int c = 0; c < 16; c++) {
            unsigned x = xl[c] ^ xh;                  // wire-basis label
            float m = PL[x & 255] * PH[x >> 8];       // |psi0| product
            int k = __popc(x) & 3;                    // phase (-i)^k
            float ar = (k & 1) ? g.y : g.x;           // G * (-i)^k
            float ai = (k & 1) ? -g.x : g.y;
            if (k & 2) { ar = -ar; ai = -ai; }
            sre[c] = fmaf(m, ar, sre[c]);
            sim[c] = fmaf(m, ai, sim[c]);
        }
    }

    // ---- stage 4: RX gates, qubits 0..3 in registers ----
#pragma unroll
    for (int q = 0; q < 4; q++) {
        float cc = c2[q], ss = s2[q];
        int bit = 1 << q;
#pragma unroll
        for (int c = 0; c < 16; c++) {
            if (!(c & bit)) {
                int d = c | bit;
                float n0r = fmaf( ss, sim[d], cc * sre[c]);
                float n0i = fmaf(-ss, sre[d], cc * sim[c]);
                float n1r = fmaf( ss, sim[c], cc * sre[d]);
                float n1i = fmaf(-ss, sre[c], cc * sim[d]);
                sre[c] = n0r; sim[c] = n0i; sre[d] = n1r; sim[d] = n1i;
            }
        }
    }

    // ---- qubits 4..8 via warp shuffles (lane bits) ----
#pragma unroll
    for (int q = 4; q < 9; q++) {
        float cc = c2[q], ss = s2[q];
        int lb = 1 << (q - 4);
#pragma unroll
        for (int c = 0; c < 16; c++) {
            float orr = __shfl_xor_sync(0xffffffffu, sre[c], lb);
            float oii = __shfl_xor_sync(0xffffffffu, sim[c], lb);
            float nr = fmaf( ss, oii, cc * sre[c]);
            float ni = fmaf(-ss, orr, cc * sim[c]);
            sre[c] = nr; sim[c] = ni;
        }
    }

    // ---- one SMEM transpose: make bits {0,9,10,11} register-local ----
#pragma unroll
    for (int c = 0; c < 16; c++) {
        int low = (wq << 9) | (lane << 4) | c;
        st[low + (low >> 4)] = make_float2(sre[c], sim[c]);
    }
    __syncthreads();
#pragma unroll
    for (int j = 0; j < 16; j++) {
        int low = ((j >> 1) << 9) | (tid << 1) | (j & 1);
        float2 v = st[low + (low >> 4)];
        sre[j] = v.x; sim[j] = v.y;
    }

    // ---- qubits 9..11 in registers (j bits 1..3) ----
#pragma unroll
    for (int q = 9; q < 12; q++) {
        float cc = c2[q], ss = s2[q];
        int bit = 1 << (q - 8);
#pragma unroll
        for (int c = 0; c < 16; c++) {
            if (!(c & bit)) {
                int d = c | bit;
                float n0r = fmaf( ss, sim[d], cc * sre[c]);
                float n0i = fmaf(-ss, sre[d], cc * sim[c]);
                float n1r = fmaf( ss, sim[c], cc * sre[d]);
                float n1i = fmaf(-ss, sre[c], cc * sim[d]);
                sre[c] = n0r; sim[c] = n0i; sre[d] = n1r; sim[d] = n1i;
            }
        }
    }

    // ---- stage 5: probabilities + Z-string signs (prefix parity) ----
    float acc[16];
#pragma unroll
    for (int i = 0; i < 16; i++) acc[i] = 0.f;
#pragma unroll
    for (int j = 0; j < 16; j++) {
        unsigned y = (unsigned)((h << 12) | ((j >> 1) << 9) | (tid << 1) | (j & 1));
        float p = fmaf(sre[j], sre[j], sim[j] * sim[j]);
        unsigned t = y;
        t ^= t << 1; t ^= t << 2; t ^= t << 4; t ^= t << 8;  // bit i of t = parity(y bits 0..i)
        unsigned p0 = ((t >> 15) ^ y) & 1;                   // parity of bits 1..15
        acc[0] += p0 ? -p : p;
#pragma unroll
        for (int i = 1; i < 16; i++)
            acc[i] += ((t >> i) & 1) ? -p : p;
    }

    // ---- block reduction (deterministic, no atomics) ----
#pragma unroll
    for (int i = 0; i < 16; i++) {
        float v = acc[i];
#pragma unroll
        for (int off = 16; off; off >>= 1)
            v += __shfl_down_sync(0xffffffffu, v, off);
        if (lane == 0) wsum[wq][i] = v;
    }
    __syncthreads();
    if (tid < 16) {
        float s = 0.f;
#pragma unroll
        for (int k = 0; k < 8; k++) s += wsum[k][tid];
        g_partial[(h * BATCH + b) * NQ + tid] = s;
    }
}

__global__ void reduce_kernel(float* __restrict__ out) {
    int idx = blockIdx.x * blockDim.x + threadIdx.x;
    if (idx < BATCH * NQ) {
        float s = 0.f;
#pragma unroll
        for (int hh = 0; hh < NH; hh++)
            s += g_partial[hh * (BATCH * NQ) + idx];
        out[idx] = s;
    }
}

extern "C" void kernel_launch(void* const* d_in, const int* in_sizes, int n_in,
                              void* d_out, int out_size) {
    const float* z      = (const float*)d_in[0];   // [512,16]
    const float* params = (const float*)d_in[1];   // [16]
    const float* w      = (const float*)d_in[2];   // ent_weights [2,16]
    float* out = (float*)d_out;                    // [512,16] float32

    dim3 grid(NH, BATCH);
    qsim_kernel<<<grid, THREADS>>>(z, params, w);
    reduce_kernel<<<(BATCH * NQ + 255) / 256, 256>>>(out);
}

// round 5
// speedup vs baseline: 33.5100x; 33.5100x over previous
#include <cuda_runtime.h>

#define NQ 16
#define BATCH 512
#define CAP 2048   // max terms per output (analysis says <= 256; 8x headroom)

__device__ float          g_coeff[NQ][CAP];
__device__ unsigned short g_ymask[NQ][CAP];
__device__ int            g_count[NQ];
__device__ unsigned short g_zmask[NQ];

// ---------------------------------------------------------------------------
// Kernel A: build the surviving Pauli terms for each output i.
//   Circuit: psi = C2 R2 C1 R_a |0>,  C = CNOT ring (control q, target q+1,
//   applied q=0..15).  Conjugation C† P C processes gates g=15..0 with
//   symplectic updates  x_t ^= x_c ,  z_c ^= z_t  and the A-G sign rule.
//   Survivors (no X letter) of the 2^|S_i| ZY-expansions form a linear
//   subspace in the Y-mask 'a'; we null-space-eliminate and enumerate it.
// ---------------------------------------------------------------------------
__global__ __launch_bounds__(512) void build_terms(const float* __restrict__ w)
{
    __shared__ float ct[NQ], st[NQ];                 // cos/sin of layer-1 theta
    __shared__ unsigned short basis_s[NQ][16];
    __shared__ int dim_s[NQ];

    const int tid = threadIdx.x;
    const int lane = tid & 31;
    const int i = tid >> 5;                          // output index (warp per i)

    if (tid < NQ) { ct[tid] = cosf(w[NQ + tid]); st[tid] = sinf(w[NQ + tid]); }
    __syncthreads();

    // S_i = support after C2-conjugation of Z_i (pure-Z string)
    const unsigned S = (i == 0) ? 0xFFFEu : ((1u << (i + 1)) - 1u);

    // z-evolution through C1-conjugation (independent of the Y mask)
    unsigned zz = S;
    for (int g = 15; g >= 0; g--) {
        int t = (g + 1) & 15;
        zz ^= ((zz >> t) & 1u) << g;                 // z_c ^= z_t  (c = g)
    }

    // init basis = unit vectors spanning S
    if (lane == 0) {
        int d0 = 0;
        for (int q = 0; q < 16; q++)
            if ((S >> q) & 1) basis_s[i][d0++] = (unsigned short)(1u << q);
        dim_s[i] = d0;
    }
    __syncwarp();

    // eliminate: for every q with zz_q == 0, require x'_q(a) == 0
    for (int q = 0; q < 16; q++) {
        if ((zz >> q) & 1) continue;
        int d = dim_s[i];
        unsigned dot = 0;
        if (lane < d) {
            unsigned x = basis_s[i][lane];
            for (int g = 15; g >= 0; g--) {          // x_t ^= x_c
                int t = (g + 1) & 15;
                x ^= ((x >> g) & 1u) << t;
            }
            dot = (x >> q) & 1u;
        }
        unsigned bal = __ballot_sync(0xffffffffu, dot);
        if (bal) {
            int piv = __ffs(bal) - 1;
            unsigned short pv = basis_s[i][piv];
            __syncwarp();
            if (dot && lane != piv) basis_s[i][lane] = (unsigned short)(basis_s[i][lane] ^ pv);
            __syncwarp();
            if (lane == 0) { basis_s[i][piv] = basis_s[i][d - 1]; dim_s[i] = d - 1; }
        }
        __syncwarp();
    }
    __syncwarp();

    const int d = dim_s[i];
    int cnt = 1 << d;
    if (cnt > CAP) cnt = CAP;                        // defensive (never hit)
    if (lane == 0) { g_count[i] = cnt; g_zmask[i] = (unsigned short)zz; }

    // enumerate the solution space; every element survives by construction
    for (int j = lane; j < cnt; j += 32) {
        unsigned a = 0;
        for (int k = 0; k < d; k++)
            if ((j >> k) & 1) a ^= basis_s[i][k];

        // full symplectic conjugation with sign tracking
        unsigned x = a, z = S, sgn = 0;
        for (int g = 15; g >= 0; g--) {
            int c = g, t = (g + 1) & 15;
            unsigned xc = (x >> c) & 1u, zt = (z >> t) & 1u;
            unsigned xt = (x >> t) & 1u, zc = (z >> c) & 1u;
            sgn ^= xc & zt & (xt ^ zc ^ 1u);
            x ^= xc << t;
            z ^= zt << c;
        }

        float coeff = sgn ? -1.f : 1.f;
#pragma unroll
        for (int q = 0; q < 16; q++)
            if ((S >> q) & 1)
                coeff *= ((a >> q) & 1) ? st[q] : ct[q];

        g_coeff[i][j] = coeff;
        g_ymask[i][j] = (unsigned short)x;           // final Y positions
    }
}

// ---------------------------------------------------------------------------
// Kernel B: per-sample evaluation.
//   <Z_i>_b = sum_t coeff_t * prod_{q in zz_i} ( ym_q ? -sin(phi_q) : cos(phi_q) )
//   with phi_q = z[b,q] + params[q] + ent_weights[0,q].
// ---------------------------------------------------------------------------
__global__ __launch_bounds__(512) void eval_kernel(
    const float* __restrict__ zin,
    const float* __restrict__ params,
    const float* __restrict__ w,
    float* __restrict__ out)
{
    __shared__ float cp[NQ], yp[NQ];
    const int b = blockIdx.x;
    const int tid = threadIdx.x;
    const int lane = tid & 31;
    const int i = tid >> 5;

    if (tid < NQ) {
        float phi = zin[b * NQ + tid] + params[tid] + w[tid];
        cp[tid] = cosf(phi);                         // <Z> on RX(phi)|0>
        yp[tid] = -sinf(phi);                        // <Y> on RX(phi)|0>
    }
    __syncthreads();

    const unsigned zm = g_zmask[i];
    const int cnt = g_count[i];

    float acc = 0.f;
    for (int t = lane; t < cnt; t += 32) {
        float prod = g_coeff[i][t];
        unsigned ym = g_ymask[i][t];
#pragma unroll
        for (int q = 0; q < 16; q++) {
            float f = ((zm >> q) & 1)
                        ? (((ym >> q) & 1) ? yp[q] : cp[q])
                        : 1.0f;
            prod *= f;
        }
        acc += prod;
    }
#pragma unroll
    for (int off = 16; off; off >>= 1)
        acc += __shfl_down_sync(0xffffffffu, acc, off);
    if (lane == 0) out[b * NQ + i] = acc;
}

extern "C" void kernel_launch(void* const* d_in, const int* in_sizes, int n_in,
                              void* d_out, int out_size) {
    const float* z      = (const float*)d_in[0];   // [512,16]
    const float* params = (const float*)d_in[1];   // [16]
    const float* w      = (const float*)d_in[2];   // ent_weights [2,16]
    float* out = (float*)d_out;                    // [512,16] float32

    build_terms<<<1, 512>>>(w);
    eval_kernel<<<BATCH, 512>>>(z, params, w, out);
}